// round 2
// baseline (speedup 1.0000x reference)
#include <cuda_runtime.h>
#include <math.h>

#define NQ 14
#define NS (1 << NQ)      // 16384 amplitudes
#define NL 4
#define NC 10
#define BATCH 1024
#define THREADS 1024

// CNOT-ring permutation: new basis label for old label a.
// Wire w <-> bit (13-w). Ring CNOT(0,1),(1,2),...,(13,0) makes wire t (t>=1)
// the prefix-XOR b0^..^bt, and wire 0 = b1^..^b13.
// In bit space: bit p (p<=12) of P(a) = parity(a>>p); bit13 = parity(a&0x1FFF).
__device__ __forceinline__ unsigned permring(unsigned a) {
    unsigned t = a ^ (a >> 1);
    t ^= t >> 2;
    t ^= t >> 4;
    t ^= t >> 8;                      // bit p of t = parity of bits >= p
    return (t & 0x1FFFu) | ((((t ^ (a >> 13)) & 1u) << 13));
}

// RX butterfly: [c, -i s; -i s, c] applied to (u, v). Symmetric in u/v.
__device__ __forceinline__ void rxg(float2 &u, float2 &v, float c, float s) {
    float2 nu, nv;
    nu.x = fmaf(c, u.x,  s * v.y);
    nu.y = fmaf(c, u.y, -s * v.x);
    nv.x = fmaf(c, v.x,  s * u.y);
    nv.y = fmaf(c, v.y, -s * u.x);
    u = nu; v = nv;
}

__global__ void __launch_bounds__(THREADS, 1)
qsim_kernel(const float* __restrict__ x,
            const float* __restrict__ qp,
            const float* __restrict__ fcw,
            const float* __restrict__ fcb,
            float* __restrict__ out) {
    extern __shared__ float2 st[];          // NS amplitudes (128 KB)
    __shared__ float cq[NL * NQ], sq[NL * NQ];
    __shared__ float cx[NQ], sx[NQ];
    __shared__ float hi[128], lo[128];
    __shared__ float zpart[32][NQ];
    __shared__ float zfin[NQ];

    const int tid = threadIdx.x;
    const int b   = blockIdx.x;

    // ---- per-layer RX angles (shared across batch) ----
    if (tid < NL * NQ) {
        float a = 0.5f * qp[tid];
        cq[tid] = cosf(a);
        sq[tid] = sinf(a);
    }
    // ---- per-sample RY half-angles ----
    if (tid >= 64 && tid < 64 + NQ) {
        int w = tid - 64;
        float a = 0.5f * x[b * NQ + w];
        cx[w] = cosf(a);
        sx[w] = sinf(a);
    }
    __syncthreads();

    // ---- sub-product tables for product-state init ----
    // i = amplitude index; hi part = i>>7 (bits 7..13 = wires 6..0),
    // lo part = i&127 (bits 0..6 = wires 13..7).
    if (tid < 128) {
        float p = 1.0f;
        #pragma unroll
        for (int q = 0; q < 7; q++)
            p *= ((tid >> q) & 1) ? sx[6 - q] : cx[6 - q];
        hi[tid] = p;
    } else if (tid < 256) {
        int m = tid - 128;
        float p = 1.0f;
        #pragma unroll
        for (int q = 0; q < 7; q++)
            p *= ((m >> q) & 1) ? sx[13 - q] : cx[13 - q];
        lo[m] = p;
    }
    __syncthreads();

    // ---- initialize state: |psi> = RY(x) |0...0>, real product state ----
    #pragma unroll
    for (int it = 0; it < NS / THREADS; it++) {
        int i = tid + it * THREADS;
        st[i] = make_float2(hi[i >> 7] * lo[i & 127], 0.0f);
    }
    __syncthreads();

    // ---- 4 entangler layers: 14 RX (5 fused passes) + CNOT ring (fused perm) ----
    for (int l = 0; l < NL; l++) {
        const float* cl = cq + l * NQ;
        const float* sl = sq + l * NQ;

        // 4 triple passes: wires (3t, 3t+1, 3t+2) -> bit positions (13-3t, 12-3t, 11-3t)
        #pragma unroll
        for (int t = 0; t < 4; t++) {
            const int sh = 11 - 3 * t;
            const float c0 = cl[3 * t],     s0 = sl[3 * t];
            const float c1 = cl[3 * t + 1], s1 = sl[3 * t + 1];
            const float c2 = cl[3 * t + 2], s2 = sl[3 * t + 2];
            #pragma unroll
            for (int it = 0; it < (NS / 8) / THREADS; it++) {
                const int g = tid + it * THREADS;
                const int base = (g & ((1 << sh) - 1)) | ((g >> sh) << (sh + 3));
                float2 a[8];
                #pragma unroll
                for (int j = 0; j < 8; j++) a[j] = st[base | (j << sh)];
                // wire 3t+2 = j bit0
                rxg(a[0], a[1], c2, s2); rxg(a[2], a[3], c2, s2);
                rxg(a[4], a[5], c2, s2); rxg(a[6], a[7], c2, s2);
                // wire 3t+1 = j bit1
                rxg(a[0], a[2], c1, s1); rxg(a[1], a[3], c1, s1);
                rxg(a[4], a[6], c1, s1); rxg(a[5], a[7], c1, s1);
                // wire 3t = j bit2
                rxg(a[0], a[4], c0, s0); rxg(a[1], a[5], c0, s0);
                rxg(a[2], a[6], c0, s0); rxg(a[3], a[7], c0, s0);
                #pragma unroll
                for (int j = 0; j < 8; j++) st[base | (j << sh)] = a[j];
            }
            __syncthreads();
        }

        // pair pass: wires 12,13 (bits 1,0), with CNOT-ring permutation fused
        // into the scatter write (read all -> sync -> scatter write).
        {
            const float c12 = cl[12], s12 = sl[12];
            const float c13 = cl[13], s13 = sl[13];
            float2 a[4][4];
            #pragma unroll
            for (int k = 0; k < 4; k++) {
                const int g = tid + k * THREADS;
                float4 u = *(const float4*)(st + 4 * g);
                float4 v = *(const float4*)(st + 4 * g + 2);
                a[k][0] = make_float2(u.x, u.y);
                a[k][1] = make_float2(u.z, u.w);
                a[k][2] = make_float2(v.x, v.y);
                a[k][3] = make_float2(v.z, v.w);
                rxg(a[k][0], a[k][1], c13, s13);   // wire 13 = bit 0
                rxg(a[k][2], a[k][3], c13, s13);
                rxg(a[k][0], a[k][2], c12, s12);   // wire 12 = bit 1
                rxg(a[k][1], a[k][3], c12, s12);
            }
            __syncthreads();
            #pragma unroll
            for (int k = 0; k < 4; k++) {
                const unsigned g4 = 4u * (unsigned)(tid + k * THREADS);
                #pragma unroll
                for (int j = 0; j < 4; j++) st[permring(g4 | j)] = a[k][j];
            }
            __syncthreads();
        }
    }

    // ---- measurement: <Z_w> = sum_a (1 - 2*bit_{13-w}(a)) |amp(a)|^2 ----
    // i = m*1024 + tid: bits 0..9 = tid (wires 4..13 fixed per thread),
    // bits 10..13 = m (wires 0..3).
    float S[16];
    #pragma unroll
    for (int m = 0; m < 16; m++) {
        float2 v = st[m * THREADS + tid];
        S[m] = fmaf(v.x, v.x, v.y * v.y);
    }
    float Stot = 0.0f;
    #pragma unroll
    for (int m = 0; m < 16; m++) Stot += S[m];

    float z[NQ];
    #pragma unroll
    for (int w = 0; w < 4; w++) {
        float t = 0.0f;
        #pragma unroll
        for (int m = 0; m < 16; m++)
            t += ((m >> (3 - w)) & 1) ? -S[m] : S[m];
        z[w] = t;
    }
    #pragma unroll
    for (int w = 4; w < NQ; w++)
        z[w] = ((tid >> (13 - w)) & 1) ? -Stot : Stot;

    // deterministic two-level reduction
    const int lane = tid & 31, warp = tid >> 5;
    #pragma unroll
    for (int w = 0; w < NQ; w++) {
        float v = z[w];
        #pragma unroll
        for (int o = 16; o > 0; o >>= 1)
            v += __shfl_xor_sync(0xFFFFFFFFu, v, o);
        if (lane == 0) zpart[warp][w] = v;
    }
    __syncthreads();
    if (tid < NQ) {
        float s = 0.0f;
        #pragma unroll
        for (int u = 0; u < 32; u++) s += zpart[u][tid];
        zfin[tid] = s;
    }
    __syncthreads();

    // ---- linear head: logits = z @ fc_w^T + fc_b ----
    if (tid < NC) {
        float s = fcb[tid];
        #pragma unroll
        for (int w = 0; w < NQ; w++)
            s = fmaf(zfin[w], fcw[tid * NQ + w], s);
        out[b * NC + tid] = s;
    }
}

extern "C" void kernel_launch(void* const* d_in, const int* in_sizes, int n_in,
                              void* d_out, int out_size) {
    const float* x   = (const float*)d_in[0];   // [1024,14]
    const float* qp  = (const float*)d_in[1];   // [4,14]
    const float* fcw = (const float*)d_in[2];   // [10,14]
    const float* fcb = (const float*)d_in[3];   // [10]
    float* out = (float*)d_out;                 // [1024,10]

    cudaFuncSetAttribute(qsim_kernel,
                         cudaFuncAttributeMaxDynamicSharedMemorySize,
                         NS * (int)sizeof(float2));
    qsim_kernel<<<BATCH, THREADS, NS * sizeof(float2)>>>(x, qp, fcw, fcb, out);
}

// round 4
// speedup vs baseline: 1.7238x; 1.7238x over previous
#include <cuda_runtime.h>
#include <math.h>

#define NQ 14
#define NS (1 << NQ)
#define NL 4
#define NC 10
#define THREADS 1024

#define HD __host__ __device__

// ======================= compile-time GF(2) machinery =======================
struct Mat { unsigned c[NQ]; };

// Forward CNOT-ring permutation in bit space (verified in R1 kernel).
HD constexpr unsigned permP(unsigned a) {
    unsigned t = a ^ (a >> 1);
    t ^= t >> 2; t ^= t >> 4; t ^= t >> 8;
    return (t & 0x1FFFu) | (((t ^ (a >> 13)) & 1u) << 13);
}
HD constexpr Mat buildP() { Mat m{}; for (int k = 0; k < NQ; k++) m.c[k] = permP(1u << k); return m; }
HD constexpr unsigned mapv(const Mat& m, unsigned a) {
    unsigned r = 0; for (int k = 0; k < NQ; k++) if ((a >> k) & 1u) r ^= m.c[k]; return r;
}
HD constexpr Mat mmul(const Mat& A, const Mat& B) {
    Mat C{}; for (int k = 0; k < NQ; k++) C.c[k] = mapv(A, B.c[k]); return C;
}
HD constexpr Mat minv(Mat a) {
    Mat e{}; for (int i = 0; i < NQ; i++) e.c[i] = 1u << i;
    for (int r = 0; r < NQ; r++) {
        int p = r; while (!((a.c[p] >> r) & 1u)) ++p;
        unsigned t = a.c[r]; a.c[r] = a.c[p]; a.c[p] = t;
        t = e.c[r]; e.c[r] = e.c[p]; e.c[p] = t;
        for (int q = 0; q < NQ; q++)
            if (q != r && ((a.c[q] >> r) & 1u)) { a.c[q] ^= a.c[r]; e.c[q] ^= e.c[r]; }
    }
    return e;
}
HD constexpr Mat pinvPow(int l) {
    Mat r{}; for (int i = 0; i < NQ; i++) r.c[i] = 1u << i;
    Mat pi = minv(buildP());
    for (int i = 0; i < l; i++) r = mmul(pi, r);
    return r;
}
// Mask for RX on wire w in layer l (0-based), in the unpermuted storage frame.
HD constexpr unsigned lmask(int l, int w) { return mapv(pinvPow(l), 1u << (13 - w)); }

// ---- pass grouping: 12 within-layer groups of 4 wires + 2 cross-layer ----
// Leftover wires {12,13} paired across layers {0,2} and {1,3}: adjacent-layer
// pairing is rank-3 (P(e0^e1)=e1), non-adjacent is rank-4 (static_assert below).
struct Gates { unsigned m[4]; int ang[4]; };
HD constexpr Gates passGates(int p) {
    Gates g{};
    if (p < 12) {
        int l = p / 3, gr = p % 3;
        for (int i = 0; i < 4; i++) { int w = gr * 4 + i; g.m[i] = lmask(l, w); g.ang[i] = l * NQ + w; }
    } else {
        for (int i = 0; i < 4; i++) {
            int l = (p - 12) + 2 * (i >> 1), w = 12 + (i & 1);
            g.m[i] = lmask(l, w); g.ang[i] = l * NQ + w;
        }
    }
    return g;
}
HD constexpr int topbit(unsigned x) { int t = -1; for (int i = 0; i < NQ; i++) if ((x >> i) & 1u) t = i; return t; }
// Column echelon with highest-bit pivot preference; returns pivot-position bitmask.
HD constexpr unsigned pivotsOf(Gates g) {
    unsigned b[4] = { g.m[0], g.m[1], g.m[2], g.m[3] };
    unsigned piv = 0;
    for (int i = 0; i < 4; i++) {
        int best = -1, bb = -1;
        for (int k = i; k < 4; k++) { int tb = topbit(b[k]); if (tb > bb) { bb = tb; best = k; } }
        if (bb < 0) return piv;
        unsigned t = b[i]; b[i] = b[best]; b[best] = t;
        piv |= 1u << bb;
        for (int k = 0; k < 4; k++) if (k != i && ((b[k] >> bb) & 1u)) b[k] ^= b[i];
    }
    return piv;
}
HD constexpr int popc14(unsigned x) { int c = 0; for (int i = 0; i < NQ; i++) c += (x >> i) & 1u; return c; }
HD constexpr bool allRank() {
    for (int p = 0; p < 14; p++) if (popc14(pivotsOf(passGates(p))) != 4) return false;
    return true;
}
static_assert(allRank(), "a pass's 4 masks are linearly dependent - regroup");

// ---- global XOR swizzle chosen so every pass is bank-conflict-free ----
// Condition: images of the 5 lowest free bits under phys-low4 have GF(2) rank 4
// -> 32 lanes hit all 16 bank-pairs exactly twice (optimal for LDS.64).
HD constexpr bool passOK(int p, int s) {
    unsigned piv = pivotsOf(passGates(p));
    int F[5] = {0, 0, 0, 0, 0};
    int n = 0;
    for (int bit = 0; bit < NQ && n < 5; bit++) if (!((piv >> bit) & 1u)) F[n++] = bit;
    unsigned bas[4] = {0, 0, 0, 0}; int rank = 0;
    for (int i = 0; i < 5; i++) {
        unsigned x = ((1u << F[i]) ^ ((1u << F[i]) >> s)) & 0xFu;
        for (int rr = 3; rr >= 0; rr--) {
            if ((x >> rr) & 1u) {
                if (bas[rr]) { x ^= bas[rr]; }
                else { bas[rr] = x; rank++; break; }
            }
        }
    }
    return rank == 4;
}
HD constexpr int pickS() {
    for (int s = 4; s <= 10; s++) {
        bool ok = true;
        for (int p = 0; p < 14; p++) if (!passOK(p, s)) ok = false;
        if (ok) return s;
    }
    return -1;
}
constexpr int SWs = pickS();
static_assert(SWs >= 0, "no conflict-free swizzle found");
HD constexpr unsigned physm(unsigned a) { return a ^ ((a >> SWs) & 0xFu); }

// ---- per-pass constants: XOR tables + bit-deposit plan for coset reps ----
struct PassC {
    unsigned cj[16];   // logical XOR-combination of masks per j
    unsigned pc[16];   // phys(cj) (swizzle is linear -> addr = phys(rep) ^ pc[j])
    int ang[4];
    int nrun; int src[6]; int dst[6]; unsigned msk[6];
};
HD constexpr PassC makePassC(int p) {
    PassC d{};
    Gates g = passGates(p);
    for (int i = 0; i < 4; i++) d.ang[i] = g.ang[i];
    for (int j = 0; j < 16; j++) {
        unsigned c = 0;
        for (int b = 0; b < 4; b++) if ((j >> b) & 1) c ^= g.m[b];
        d.cj[j] = c; d.pc[j] = physm(c);
    }
    unsigned piv = pivotsOf(g);
    int F[10] = {0, 0, 0, 0, 0, 0, 0, 0, 0, 0};
    int n = 0;
    for (int bit = 0; bit < NQ; bit++) if (!((piv >> bit) & 1u)) F[n++] = bit;
    int r = 0, i = 0;
    while (i < 10) {                      // contiguous runs -> few shift/mask terms
        int jj = i;
        while (jj + 1 < 10 && F[jj + 1] == F[jj] + 1) jj++;
        d.src[r] = i; d.dst[r] = F[i]; d.msk[r] = (1u << (jj - i + 1)) - 1u; r++;
        i = jj + 1;
    }
    d.nrun = r;
    return d;
}

// ---- measurement constants: <Z_w> signs from rows of P^4, Walsh indices ----
struct MeasC { int kw[NQ]; unsigned rw[NQ]; };
HD constexpr int par14(unsigned x) { int p = 0; for (int i = 0; i < NQ; i++) p ^= (x >> i) & 1u; return p; }
HD constexpr unsigned rowm(const Mat& m, int bit) {
    unsigned r = 0; for (int k = 0; k < NQ; k++) r |= ((m.c[k] >> bit) & 1u) << k; return r;
}
HD constexpr MeasC makeMeasC() {
    MeasC mc{};
    Mat p = buildP(); Mat p2 = mmul(p, p); Mat p4 = mmul(p2, p2);
    Gates g = passGates(13);
    for (int w = 0; w < NQ; w++) {
        unsigned r = rowm(p4, 13 - w);
        mc.rw[w] = r;
        int k = 0;
        for (int b = 0; b < 4; b++) k |= par14(g.m[b] & r) << b;   // sign LUT is linear in j
        mc.kw[w] = k;
    }
    return mc;
}

// ============================ device code ===================================
__device__ __forceinline__ void rxg(float2& u, float2& v, float c, float s) {
    float2 nu, nv;
    nu.x = fmaf(c, u.x,  s * v.y);
    nu.y = fmaf(c, u.y, -s * v.x);
    nv.x = fmaf(c, v.x,  s * u.y);
    nv.y = fmaf(c, v.y, -s * u.x);
    u = nu; v = nv;
}

template<int P>
__device__ __forceinline__ unsigned passRun(float2* __restrict__ st, int tid,
        const float* __restrict__ cq, const float* __restrict__ sq,
        const float* __restrict__ hi, const float* __restrict__ lo,
        float* __restrict__ Sv)
{
    constexpr PassC pd = makePassC(P);
    unsigned rep = 0;
    #pragma unroll
    for (int r = 0; r < pd.nrun; r++)
        rep |= (((unsigned)tid >> pd.src[r]) & pd.msk[r]) << pd.dst[r];
    unsigned prep = rep ^ ((rep >> SWs) & 0xFu);

    float2 a[16];
    if (P == 0) {
        // init fold: product state computed from tables, no state read
        #pragma unroll
        for (int j = 0; j < 16; j++) {
            unsigned ix = rep ^ pd.cj[j];
            a[j] = make_float2(hi[ix >> 7] * lo[ix & 127], 0.0f);
        }
    } else {
        #pragma unroll
        for (int j = 0; j < 16; j++) a[j] = st[prep ^ pd.pc[j]];
    }

    float C[4], Sg[4];
    #pragma unroll
    for (int i = 0; i < 4; i++) { C[i] = cq[pd.ang[i]]; Sg[i] = sq[pd.ang[i]]; }

    #pragma unroll
    for (int b = 0; b < 4; b++) {
        #pragma unroll
        for (int j = 0; j < 16; j++)
            if (!((j >> b) & 1)) rxg(a[j], a[j | (1 << b)], C[b], Sg[b]);
    }

    if (P == 13) {
        // measurement fold: probabilities in registers, no state write
        #pragma unroll
        for (int j = 0; j < 16; j++) Sv[j] = fmaf(a[j].x, a[j].x, a[j].y * a[j].y);
    } else {
        #pragma unroll
        for (int j = 0; j < 16; j++) st[prep ^ pd.pc[j]] = a[j];
    }
    return rep;
}

__global__ void __launch_bounds__(THREADS, 1)
qsim_kernel(const float* __restrict__ x, const float* __restrict__ qp,
            const float* __restrict__ fcw, const float* __restrict__ fcb,
            float* __restrict__ out)
{
    extern __shared__ float2 st[];                 // 16384 amps, 128 KB
    __shared__ float cq[NL * NQ], sq[NL * NQ], cx[NQ], sx[NQ];
    __shared__ float hi[128], lo[128];
    __shared__ float zp[32][NQ];
    __shared__ float zf[NQ];

    const int tid = threadIdx.x, b = blockIdx.x;

    if (tid < NL * NQ) { float a = 0.5f * qp[tid]; cq[tid] = cosf(a); sq[tid] = sinf(a); }
    if (tid >= 64 && tid < 64 + NQ) {
        int w = tid - 64; float a = 0.5f * x[b * NQ + w];
        cx[w] = cosf(a); sx[w] = sinf(a);
    }
    __syncthreads();

    if (tid < 128) {
        float p = 1.0f;
        #pragma unroll
        for (int q = 0; q < 7; q++) p *= ((tid >> q) & 1) ? sx[6 - q] : cx[6 - q];
        hi[tid] = p;
    } else if (tid < 256) {
        int m = tid - 128; float p = 1.0f;
        #pragma unroll
        for (int q = 0; q < 7; q++) p *= ((m >> q) & 1) ? sx[13 - q] : cx[13 - q];
        lo[m] = p;
    }
    __syncthreads();

    float Sv[16];
    passRun<0>(st, tid, cq, sq, hi, lo, Sv);  __syncthreads();
    passRun<1>(st, tid, cq, sq, hi, lo, Sv);  __syncthreads();
    passRun<2>(st, tid, cq, sq, hi, lo, Sv);  __syncthreads();
    passRun<3>(st, tid, cq, sq, hi, lo, Sv);  __syncthreads();
    passRun<4>(st, tid, cq, sq, hi, lo, Sv);  __syncthreads();
    passRun<5>(st, tid, cq, sq, hi, lo, Sv);  __syncthreads();
    passRun<6>(st, tid, cq, sq, hi, lo, Sv);  __syncthreads();
    passRun<7>(st, tid, cq, sq, hi, lo, Sv);  __syncthreads();
    passRun<8>(st, tid, cq, sq, hi, lo, Sv);  __syncthreads();
    passRun<9>(st, tid, cq, sq, hi, lo, Sv);  __syncthreads();
    passRun<10>(st, tid, cq, sq, hi, lo, Sv); __syncthreads();
    passRun<11>(st, tid, cq, sq, hi, lo, Sv); __syncthreads();
    passRun<12>(st, tid, cq, sq, hi, lo, Sv); __syncthreads();
    unsigned rep13 = passRun<13>(st, tid, cq, sq, hi, lo, Sv);

    // 16-point Walsh-Hadamard: all +/- subset sums of Sv at once
    #pragma unroll
    for (int stp = 1; stp < 16; stp <<= 1) {
        #pragma unroll
        for (int j = 0; j < 16; j++)
            if (!(j & stp)) { float u = Sv[j], v = Sv[j | stp]; Sv[j] = u + v; Sv[j | stp] = u - v; }
    }

    constexpr MeasC mc = makeMeasC();
    const int lane = tid & 31, warp = tid >> 5;
    #pragma unroll
    for (int w = 0; w < NQ; w++) {
        float v = Sv[mc.kw[w]];
        v = (__popc(rep13 & mc.rw[w]) & 1) ? -v : v;
        #pragma unroll
        for (int o = 16; o > 0; o >>= 1)
            v += __shfl_xor_sync(0xFFFFFFFFu, v, o);
        if (lane == 0) zp[warp][w] = v;
    }
    __syncthreads();
    if (tid < NQ) {
        float s = 0.0f;
        #pragma unroll
        for (int u = 0; u < 32; u++) s += zp[u][tid];
        zf[tid] = s;
    }
    __syncthreads();

    if (tid < NC) {
        float s = fcb[tid];
        #pragma unroll
        for (int w = 0; w < NQ; w++) s = fmaf(zf[w], fcw[tid * NQ + w], s);
        out[b * NC + tid] = s;
    }
}

extern "C" void kernel_launch(void* const* d_in, const int* in_sizes, int n_in,
                              void* d_out, int out_size) {
    const float* x   = (const float*)d_in[0];   // [1024,14]
    const float* qp  = (const float*)d_in[1];   // [4,14]
    const float* fcw = (const float*)d_in[2];   // [10,14]
    const float* fcb = (const float*)d_in[3];   // [10]
    float* out = (float*)d_out;                 // [1024,10]

    cudaFuncSetAttribute(qsim_kernel,
                         cudaFuncAttributeMaxDynamicSharedMemorySize,
                         NS * (int)sizeof(float2));
    qsim_kernel<<<1024, THREADS, NS * sizeof(float2)>>>(x, qp, fcw, fcb, out);
}

// round 5
// speedup vs baseline: 10.6612x; 6.1848x over previous
#include <cuda_runtime.h>
#include <math.h>

#define NQ 14
#define NSTATE 16384
#define NL 4
#define NG 56
#define NC 10
#define BATCH 1024

// =============== constexpr GF(2) circuit tables (frame validated in R4) ===============
struct Mat { unsigned c[NQ]; };
constexpr unsigned permP(unsigned a) {
    unsigned t = a ^ (a >> 1);
    t ^= t >> 2; t ^= t >> 4; t ^= t >> 8;
    return (t & 0x1FFFu) | (((t ^ (a >> 13)) & 1u) << 13);
}
constexpr Mat buildP() { Mat m{}; for (int k = 0; k < NQ; k++) m.c[k] = permP(1u << k); return m; }
constexpr unsigned mapv(const Mat& m, unsigned a) {
    unsigned r = 0; for (int k = 0; k < NQ; k++) if ((a >> k) & 1u) r ^= m.c[k]; return r;
}
constexpr Mat mmul(const Mat& A, const Mat& B) {
    Mat C{}; for (int k = 0; k < NQ; k++) C.c[k] = mapv(A, B.c[k]); return C;
}
constexpr Mat minv(Mat a) {
    Mat e{}; for (int i = 0; i < NQ; i++) e.c[i] = 1u << i;
    for (int r = 0; r < NQ; r++) {
        int p = r; while (!((a.c[p] >> r) & 1u)) ++p;
        unsigned t = a.c[r]; a.c[r] = a.c[p]; a.c[p] = t;
        t = e.c[r]; e.c[r] = e.c[p]; e.c[p] = t;
        for (int q = 0; q < NQ; q++)
            if (q != r && ((a.c[q] >> r) & 1u)) { a.c[q] ^= a.c[r]; e.c[q] ^= e.c[r]; }
    }
    return e;
}
constexpr Mat pinvPow(int l) {
    Mat r{}; for (int i = 0; i < NQ; i++) r.c[i] = 1u << i;
    Mat pi = minv(buildP());
    for (int i = 0; i < l; i++) r = mmul(pi, r);
    return r;
}
constexpr unsigned lmask(int l, int w) { return mapv(pinvPow(l), 1u << (13 - w)); }
constexpr unsigned rowm(const Mat& m, int bit) {
    unsigned r = 0; for (int k = 0; k < NQ; k++) r |= ((m.c[k] >> bit) & 1u) << k; return r;
}
constexpr int par14(unsigned x) { int p = 0; for (int i = 0; i < NQ; i++) p ^= (x >> i) & 1u; return p; }

struct Circ {
    unsigned mg[NG];            // X-string gate masks (storage frame)
    unsigned rw[NQ];            // Z-string measurement masks (rows of P^4)
    unsigned long long ac[NQ];  // per-w anticommute bitmask over the 56 gates
};
constexpr Circ makeCirc() {
    Circ c{};
    for (int l = 0; l < NL; l++)
        for (int w = 0; w < NQ; w++) c.mg[l * NQ + w] = lmask(l, w);
    Mat p = buildP(); Mat p2 = mmul(p, p); Mat p4 = mmul(p2, p2);
    for (int w = 0; w < NQ; w++) {
        c.rw[w] = rowm(p4, 13 - w);
        unsigned long long m = 0;
        for (int g = 0; g < NG; g++)
            if (par14(c.mg[g] & c.rw[w])) m |= 1ull << g;
        c.ac[w] = m;
    }
    return c;
}
__constant__ Circ dC = makeCirc();

// =============== static scratch (allowed: __device__ globals, no alloc) ===============
__device__ float gC[NQ * NSTATE];     // C_w tables, layout [w][v*128 + u]
__device__ float gHI[BATCH * 128];    // per-sample high-half product table (bits 7..13)
__device__ float gLO[BATCH * 128];    // per-sample low-half product table  (bits 0..6)
__device__ float gZ[BATCH * NQ];      // <Z_w> per sample

// =============== K1: C_w[u,v] = cos(sum_{g anticommuting with r_w} ±θ_g) ===============
__global__ void k_phase(const float* __restrict__ qp) {
    const int w = blockIdx.y;
    const int o = blockIdx.x * 256 + threadIdx.x;   // 0..16383, o = v*128+u
    const int u = o & 127, v = o >> 7;
    const unsigned a = ((unsigned)u << 7) | (unsigned)v;
    const unsigned long long acw = dC.ac[w];
    float d = 0.f;
    #pragma unroll
    for (int g = 0; g < NG; g++) {
        if ((acw >> g) & 1ull) {
            float t = qp[g];
            d += (__popc(a & dC.mg[g]) & 1) ? -t : t;
        }
    }
    gC[w * NSTATE + o] = cosf(d);
}

// =============== K2: per-sample product tables of chi = H^14 (RY product state) ========
__global__ void k_tables(const float* __restrict__ x) {
    __shared__ float f0[NQ], f1[NQ];
    const int b = blockIdx.x, t = threadIdx.x;
    if (t < NQ) {
        float h = 0.5f * x[b * NQ + t];
        float c = cosf(h), s = sinf(h);
        const float r = 0.70710678118654752440f;   // H * (c, s) = ((c+s), (c-s))/sqrt2
        f0[t] = (c + s) * r;
        f1[t] = (c - s) * r;
    }
    __syncthreads();
    // bit q of HI-index <-> global bit 7+q <-> wire 6-q ; LO: bit q <-> wire 13-q
    float phi = 1.f, plo = 1.f;
    #pragma unroll
    for (int q = 0; q < 7; q++) {
        phi *= ((t >> q) & 1) ? f1[6 - q]  : f0[6 - q];
        plo *= ((t >> q) & 1) ? f1[13 - q] : f0[13 - q];
    }
    gHI[b * 128 + t] = phi;
    gLO[b * 128 + t] = plo;
}

// =============== K3: Z[b,w] = HH_w^T C_w LL_w, batched bilinear contraction ============
#define BT 128            // samples per block
__global__ void __launch_bounds__(256, 1) k_contract() {
    extern __shared__ float sm[];
    float* Cs  = sm;                   // [v][u] 128x128
    float* LLs = Cs + 16384;           // [b][v] 128x130 (padded)
    float* HHs = LLs + 128 * 130;      // [b][u] 128x128
    const int w  = blockIdx.y;
    const int b0 = blockIdx.x * BT;
    const int t  = threadIdx.x;
    const unsigned rwm = dC.rw[w];
    const int rh = (int)(rwm >> 7), rl = (int)(rwm & 127);

    // fill C (coalesced float4 copy; global layout [w][v*128+u] == Cs linear)
    {
        const float4* src = (const float4*)(gC + w * NSTATE);
        float4* dst = (float4*)Cs;
        #pragma unroll
        for (int i = 0; i < 16; i++) dst[t + 256 * i] = src[t + 256 * i];
    }
    // fill LL (with rl fold) and HH (with rh fold)
    #pragma unroll
    for (int k = 0; k < 64; k++) {
        int i = t + 256 * k;            // i = b*128 + v
        int b = i >> 7, v = i & 127;
        LLs[b * 130 + v] = gLO[(b0 + b) * 128 + v] * gLO[(b0 + b) * 128 + (v ^ rl)];
        HHs[b * 128 + v] = gHI[(b0 + b) * 128 + v] * gHI[(b0 + b) * 128 + (v ^ rh)];
    }
    __syncthreads();

    const int ug = t & 15;             // u-pair group (interleaved: p = ug + 16i)
    const int bg = t >> 4;             // sample group: b = bg*8 + j
    unsigned long long acc[8][4];
    #pragma unroll
    for (int j = 0; j < 8; j++)
        #pragma unroll
        for (int i = 0; i < 4; i++) acc[j][i] = 0ull;

    for (int v = 0; v < 128; v++) {
        unsigned long long cc[4];
        #pragma unroll
        for (int i = 0; i < 4; i++)
            cc[i] = *(const unsigned long long*)(Cs + v * 128 + 2 * (ug + 16 * i));
        #pragma unroll
        for (int j = 0; j < 8; j++) {
            float ll = LLs[(bg * 8 + j) * 130 + v];
            unsigned long long llp;
            asm("mov.b64 %0, {%1, %1};" : "=l"(llp) : "f"(ll));
            #pragma unroll
            for (int i = 0; i < 4; i++)
                asm("fma.rn.f32x2 %0, %1, %2, %3;"
                    : "=l"(acc[j][i]) : "l"(cc[i]), "l"(llp), "l"(acc[j][i]));
        }
    }

    // epilogue: dot with HH over u, reduce over ug lanes, store
    #pragma unroll
    for (int j = 0; j < 8; j++) {
        float s = 0.f;
        #pragma unroll
        for (int i = 0; i < 4; i++) {
            int p = ug + 16 * i;
            float ylo, yhi;
            asm("mov.b64 {%0, %1}, %2;" : "=f"(ylo), "=f"(yhi) : "l"(acc[j][i]));
            const float* hh = HHs + (bg * 8 + j) * 128 + 2 * p;
            s = fmaf(ylo, hh[0], s);
            s = fmaf(yhi, hh[1], s);
        }
        #pragma unroll
        for (int o = 1; o < 16; o <<= 1)
            s += __shfl_xor_sync(0xFFFFFFFFu, s, o);
        if (ug == 0) gZ[(b0 + bg * 8 + j) * NQ + w] = s;
    }
}

// =============== K4: logits = Z @ fc_w^T + fc_b ===============
__global__ void k_head(const float* __restrict__ fcw, const float* __restrict__ fcb,
                       float* __restrict__ out) {
    const int b = blockIdx.x * 256 + threadIdx.x;
    float z[NQ];
    #pragma unroll
    for (int w = 0; w < NQ; w++) z[w] = gZ[b * NQ + w];
    #pragma unroll
    for (int c = 0; c < NC; c++) {
        float s = fcb[c];
        #pragma unroll
        for (int w = 0; w < NQ; w++) s = fmaf(z[w], fcw[c * NQ + w], s);
        out[b * NC + c] = s;
    }
}

extern "C" void kernel_launch(void* const* d_in, const int* in_sizes, int n_in,
                              void* d_out, int out_size) {
    const float* x   = (const float*)d_in[0];   // [1024,14]
    const float* qp  = (const float*)d_in[1];   // [4,14] row-major == gate index g
    const float* fcw = (const float*)d_in[2];   // [10,14]
    const float* fcb = (const float*)d_in[3];   // [10]
    float* out = (float*)d_out;                 // [1024,10]

    const int smK3 = (16384 + 128 * 130 + 16384) * (int)sizeof(float);  // ~193 KB
    cudaFuncSetAttribute(k_contract, cudaFuncAttributeMaxDynamicSharedMemorySize, smK3);

    k_phase<<<dim3(64, NQ), 256>>>(qp);
    k_tables<<<BATCH, 128>>>(x);
    k_contract<<<dim3(BATCH / BT, NQ), 256, smK3>>>();
    k_head<<<BATCH / 256, 256>>>(fcw, fcb, out);
}

// round 7
// speedup vs baseline: 13.8290x; 1.2971x over previous
#include <cuda_runtime.h>
#include <math.h>

#define NQ 14
#define NL 4
#define NG 56
#define NC 10
#define BATCH 1024
#define CHALF 8192          // per-w C table: 64 (inner, folded) x 128 (outer)

// =============== constexpr GF(2) circuit tables (frame validated in R4/R5) ===============
struct Mat { unsigned c[NQ]; };
constexpr unsigned permP(unsigned a) {
    unsigned t = a ^ (a >> 1);
    t ^= t >> 2; t ^= t >> 4; t ^= t >> 8;
    return (t & 0x1FFFu) | (((t ^ (a >> 13)) & 1u) << 13);
}
constexpr Mat buildP() { Mat m{}; for (int k = 0; k < NQ; k++) m.c[k] = permP(1u << k); return m; }
constexpr unsigned mapv(const Mat& m, unsigned a) {
    unsigned r = 0; for (int k = 0; k < NQ; k++) if ((a >> k) & 1u) r ^= m.c[k]; return r;
}
constexpr Mat mmul(const Mat& A, const Mat& B) {
    Mat C{}; for (int k = 0; k < NQ; k++) C.c[k] = mapv(A, B.c[k]); return C;
}
constexpr Mat minv(Mat a) {
    Mat e{}; for (int i = 0; i < NQ; i++) e.c[i] = 1u << i;
    for (int r = 0; r < NQ; r++) {
        int p = r; while (!((a.c[p] >> r) & 1u)) ++p;
        unsigned t = a.c[r]; a.c[r] = a.c[p]; a.c[p] = t;
        t = e.c[r]; e.c[r] = e.c[p]; e.c[p] = t;
        for (int q = 0; q < NQ; q++)
            if (q != r && ((a.c[q] >> r) & 1u)) { a.c[q] ^= a.c[r]; e.c[q] ^= e.c[r]; }
    }
    return e;
}
constexpr Mat pinvPow(int l) {
    Mat r{}; for (int i = 0; i < NQ; i++) r.c[i] = 1u << i;
    Mat pi = minv(buildP());
    for (int i = 0; i < l; i++) r = mmul(pi, r);
    return r;
}
constexpr unsigned lmask(int l, int w) { return mapv(pinvPow(l), 1u << (13 - w)); }
constexpr unsigned rowm(const Mat& m, int bit) {
    unsigned r = 0; for (int k = 0; k < NQ; k++) r |= ((m.c[k] >> bit) & 1u) << k; return r;
}
constexpr int par14(unsigned x) { int p = 0; for (int i = 0; i < NQ; i++) p ^= (x >> i) & 1u; return p; }
constexpr int topbit(unsigned x) { int t = -1; for (int i = 0; i < NQ; i++) if ((x >> i) & 1u) t = i; return t; }

struct Circ {
    unsigned mg[NG];            // X-string gate masks
    unsigned long long ac[NQ];  // per-w anticommute bitmask over the 56 gates
};
struct FoldC {
    int fl[NQ];                 // 1: fold on low half (inner=v/LO), 0: fold on high (inner=u/HI)
    int it[NQ];                 // bit position removed from inner index (top bit of fold mask)
    unsigned im[NQ];            // inner fold XOR mask (7-bit)
    unsigned om[NQ];            // outer fold XOR mask (7-bit, may be 0)
};
constexpr Circ makeCirc() {
    Circ c{};
    for (int l = 0; l < NL; l++)
        for (int w = 0; w < NQ; w++) c.mg[l * NQ + w] = lmask(l, w);
    Mat p = buildP(); Mat p2 = mmul(p, p); Mat p4 = mmul(p2, p2);
    for (int w = 0; w < NQ; w++) {
        unsigned rw = rowm(p4, 13 - w);
        unsigned long long m = 0;
        for (int g = 0; g < NG; g++)
            if (par14(c.mg[g] & rw)) m |= 1ull << g;
        c.ac[w] = m;
    }
    return c;
}
constexpr FoldC makeFold() {
    FoldC f{};
    Mat p = buildP(); Mat p2 = mmul(p, p); Mat p4 = mmul(p2, p2);
    for (int w = 0; w < NQ; w++) {
        unsigned rw = rowm(p4, 13 - w);
        unsigned rl = rw & 127u, rh = rw >> 7;
        if (rl) { f.fl[w] = 1; f.it[w] = topbit(rl); f.im[w] = rl; f.om[w] = rh; }
        else    { f.fl[w] = 0; f.it[w] = topbit(rh); f.im[w] = rh; f.om[w] = 0;  }
    }
    return f;
}
__constant__ Circ dC = makeCirc();
__constant__ FoldC dF = makeFold();

// =============== static scratch ===============
__device__ float gC[NQ * CHALF];      // folded C tables: [w][inner'(64) * 128 + outer]
__device__ float gHI[BATCH * 128];
__device__ float gLO[BATCH * 128];
__device__ float gZt[NQ * BATCH];     // <Z_w>, transposed [w][b] for coalesced head reads

__device__ __forceinline__ unsigned depbit(unsigned i, int t) {
    return ((i >> t) << (t + 1)) | (i & ((1u << t) - 1u));
}

// =============== K1: fused phase tables (448 blocks) + product tables (512 blocks) =====
__global__ void k_prep(const float* __restrict__ qp, const float* __restrict__ x) {
    const int t = threadIdx.x;
    if (blockIdx.x < 448) {
        __shared__ float th[NG];
        if (t < NG) th[t] = qp[t];
        __syncthreads();
        const int w = blockIdx.x >> 5;
        const int idx = ((blockIdx.x & 31) << 8) + t;     // 0..8191
        const int o = idx & 127, ip = idx >> 7;           // outer 128, inner' 64
        const unsigned inner = depbit((unsigned)ip, dF.it[w]);
        const unsigned a = dF.fl[w] ? (((unsigned)o << 7) | inner)
                                    : ((inner << 7) | (unsigned)o);
        const unsigned long long acw = dC.ac[w];
        float d = 0.f;
        #pragma unroll
        for (int g = 0; g < NG; g++)
            if ((acw >> g) & 1ull)
                d += (__popc(a & dC.mg[g]) & 1) ? -th[g] : th[g];
        gC[w * CHALF + idx] = cosf(d);
    } else {
        __shared__ float f0[2][NQ], f1[2][NQ];
        const int s = t >> 7, tl = t & 127;
        const int b = (blockIdx.x - 448) * 2 + s;
        if (tl < NQ) {
            float h = 0.5f * x[b * NQ + tl];
            float c = cosf(h), sn = sinf(h);
            const float r = 0.70710678118654752440f;     // chi = H (c, s)
            f0[s][tl] = (c + sn) * r;
            f1[s][tl] = (c - sn) * r;
        }
        __syncthreads();
        float phi = 1.f, plo = 1.f;
        #pragma unroll
        for (int q = 0; q < 7; q++) {
            phi *= ((tl >> q) & 1) ? f1[s][6 - q]  : f0[s][6 - q];
            plo *= ((tl >> q) & 1) ? f1[s][13 - q] : f0[s][13 - q];
        }
        gHI[b * 128 + tl] = phi;
        gLO[b * 128 + tl] = plo;
    }
}

// =============== K2: Z[w,b] = 2 * OUT^T C IN (folded bilinear contraction) ============
#define BT 128
__global__ void __launch_bounds__(512, 1) k_contract() {
    extern __shared__ float sm[];
    float* Cs   = sm;                  // [inner'][outer] 64x128 = 32 KB
    float* INs  = Cs + CHALF;          // [b][inner'] 128x65 (padded)
    float* OUTs = INs + 128 * 65;      // [b][outer]  128x128
    const int w = blockIdx.y, b0 = blockIdx.x * BT, t = threadIdx.x;
    const int fl = dF.fl[w], tt = dF.it[w];
    const unsigned im = dF.im[w], om = dF.om[w];
    const float* innerSrc = fl ? gLO : gHI;
    const float* outerSrc = fl ? gHI : gLO;

    {   // C copy (coalesced float4)
        const float4* src = (const float4*)(gC + w * CHALF);
        float4* dst = (float4*)Cs;
        #pragma unroll
        for (int i = 0; i < 4; i++) dst[t + 512 * i] = src[t + 512 * i];
    }
    #pragma unroll
    for (int k = 0; k < 16; k++) {     // IN table: folded half, x2 weight
        int i = t + 512 * k;
        int b = i >> 6, ii = i & 63;
        unsigned vi = depbit((unsigned)ii, tt);
        const float* s2 = innerSrc + (b0 + b) * 128;
        INs[b * 65 + ii] = 2.f * s2[vi] * s2[vi ^ im];
    }
    #pragma unroll
    for (int k = 0; k < 32; k++) {     // OUT table: full 128
        int i = t + 512 * k;
        int b = i >> 7, o = i & 127;
        const float* s2 = outerSrc + (b0 + b) * 128;
        OUTs[b * 128 + o] = s2[o] * s2[o ^ om];
    }
    __syncthreads();

    const int ug = t & 15;             // outer-pair group (interleaved: p = ug + 16i)
    const int bg = t >> 4;             // sample group: b = bg*4 + j
    unsigned long long acc[4][4];
    #pragma unroll
    for (int j = 0; j < 4; j++)
        #pragma unroll
        for (int i = 0; i < 4; i++) acc[j][i] = 0ull;

    for (int v = 0; v < 64; v++) {
        unsigned long long cc[4];
        #pragma unroll
        for (int i = 0; i < 4; i++)
            cc[i] = *(const unsigned long long*)(Cs + v * 128 + 2 * (ug + 16 * i));
        #pragma unroll
        for (int j = 0; j < 4; j++) {
            float ll = INs[(bg * 4 + j) * 65 + v];
            unsigned long long llp;
            asm("mov.b64 %0, {%1, %1};" : "=l"(llp) : "f"(ll));
            #pragma unroll
            for (int i = 0; i < 4; i++)
                asm("fma.rn.f32x2 %0, %1, %2, %3;"
                    : "=l"(acc[j][i]) : "l"(cc[i]), "l"(llp), "l"(acc[j][i]));
        }
    }

    #pragma unroll
    for (int j = 0; j < 4; j++) {
        float s = 0.f;
        #pragma unroll
        for (int i = 0; i < 4; i++) {
            int p = ug + 16 * i;
            float ylo, yhi;
            asm("mov.b64 {%0, %1}, %2;" : "=f"(ylo), "=f"(yhi) : "l"(acc[j][i]));
            float2 hh = *(const float2*)(OUTs + (bg * 4 + j) * 128 + 2 * p);
            s = fmaf(ylo, hh.x, fmaf(yhi, hh.y, s));
        }
        #pragma unroll
        for (int o = 1; o < 16; o <<= 1)
            s += __shfl_xor_sync(0xFFFFFFFFu, s, o);
        if (ug == 0) gZt[w * BATCH + b0 + bg * 4 + j] = s;
    }
}

// =============== K3: logits = Z @ fc_w^T + fc_b (coalesced) ===============
__global__ void k_head(const float* __restrict__ fcw, const float* __restrict__ fcb,
                       float* __restrict__ out) {
    const int b = blockIdx.x * 128 + threadIdx.x;
    float z[NQ];
    #pragma unroll
    for (int w = 0; w < NQ; w++) z[w] = gZt[w * BATCH + b];
    #pragma unroll
    for (int c = 0; c < NC; c++) {
        float s = fcb[c];
        #pragma unroll
        for (int w = 0; w < NQ; w++) s = fmaf(z[w], fcw[c * NQ + w], s);
        out[b * NC + c] = s;
    }
}

extern "C" void kernel_launch(void* const* d_in, const int* in_sizes, int n_in,
                              void* d_out, int out_size) {
    const float* x   = (const float*)d_in[0];   // [1024,14]
    const float* qp  = (const float*)d_in[1];   // [4,14] row-major == gate index g
    const float* fcw = (const float*)d_in[2];   // [10,14]
    const float* fcb = (const float*)d_in[3];   // [10]
    float* out = (float*)d_out;                 // [1024,10]

    const int smK = (CHALF + 128 * 65 + 128 * 128) * (int)sizeof(float);  // ~129 KB
    cudaFuncSetAttribute(k_contract, cudaFuncAttributeMaxDynamicSharedMemorySize, smK);

    k_prep<<<960, 256>>>(qp, x);
    k_contract<<<dim3(BATCH / BT, NQ), 512, smK>>>();
    k_head<<<BATCH / 128, 128>>>(fcw, fcb, out);
}